// round 1
// baseline (speedup 1.0000x reference)
#include <cuda_runtime.h>
#include <cuda_bf16.h>

// Problem constants (fixed by the dataset)
#define NN      50000      // nodes
#define EE      600000     // edges
#define DIM     128        // input/hidden dim
#define HC      256        // H*C
#define NCOLS   512        // 2*H*C (x_l | x_r)
#define NEG     0.2f
#define RMS_EPS 1e-6f

// ---------------- scratch (static device allocations) ----------------
__device__ float    g_scale[NN];                       // rms row scale
__device__ float    g_wcat[DIM * NCOLS];               // rmsw-folded [W_l | W_r]
__device__ float    g_xcat[(size_t)NN * NCOLS];        // per node: [x_l(256) | x_r(256)]
__device__ float    g_alpha[EE * 2];                   // per-edge logits
__device__ float    g_ex[EE * 2];                      // per-edge exp numerators
__device__ unsigned g_amax[NN * 2];                    // order-encoded float max
__device__ float    g_denom[NN * 2];                   // softmax denominators

// ---------------- helpers ----------------
__device__ __forceinline__ unsigned f2o(float f) {
    unsigned u = __float_as_uint(f);
    return (u & 0x80000000u) ? ~u : (u | 0x80000000u);
}
__device__ __forceinline__ float o2f(unsigned u) {
    return (u & 0x80000000u) ? __uint_as_float(u & 0x7FFFFFFFu)
                             : __uint_as_float(~u);
}
__device__ __forceinline__ float warp_sum(float v) {
    #pragma unroll
    for (int off = 16; off; off >>= 1) v += __shfl_down_sync(0xffffffffu, v, off);
    return v;
}

// ---------------- K0: init (zero d_out, amax, denom) ----------------
__global__ void k_init(float* __restrict__ out) {
    int idx = blockIdx.x * blockDim.x + threadIdx.x;
    int stride = gridDim.x * blockDim.x;
    for (int i = idx; i < NN * DIM; i += stride) out[i] = 0.0f;
    for (int i = idx; i < NN * 2; i += stride) { g_amax[i] = 0u; g_denom[i] = 0.0f; }
}

// ---------------- K1: per-row RMS scale ----------------
__global__ __launch_bounds__(256) void k_scale(const float* __restrict__ x) {
    int warp = (blockIdx.x * blockDim.x + threadIdx.x) >> 5;
    int lane = threadIdx.x & 31;
    if (warp >= NN) return;
    const float4* xr = (const float4*)(x + (size_t)warp * DIM);
    float4 v = xr[lane];
    float s = v.x * v.x + v.y * v.y + v.z * v.z + v.w * v.w;
    s = warp_sum(s);
    if (lane == 0) g_scale[warp] = rsqrtf(s * (1.0f / DIM) + RMS_EPS);
}

// ---------------- K2: fold rms_weight into [W_l | W_r] ----------------
__global__ void k_fold(const float* __restrict__ rmsw,
                       const float* __restrict__ wl,
                       const float* __restrict__ wr) {
    int idx = blockIdx.x * blockDim.x + threadIdx.x;   // over DIM*NCOLS
    if (idx >= DIM * NCOLS) return;
    int k = idx / NCOLS, j = idx % NCOLS;
    float w = (j < HC) ? wl[k * HC + j] : wr[k * HC + (j - HC)];
    g_wcat[idx] = rmsw[k] * w;
}

// ---------------- K3: GEMM  xcat = (x*scale) @ wcat  (fp32) ----------------
// BM=64, BN=64, BK=16, 256 threads, 4x4 per-thread tile
__global__ __launch_bounds__(256) void k_gemm(const float* __restrict__ x) {
    __shared__ float As[16][64];   // transposed: [k][m]
    __shared__ float Bs[16][64];

    int t  = threadIdx.x;
    int n0 = blockIdx.x * 64;
    int m0 = blockIdx.y * 64;
    int tx = t & 15, ty = t >> 4;          // 16x16 thread grid

    float acc[4][4];
    #pragma unroll
    for (int i = 0; i < 4; i++)
        #pragma unroll
        for (int j = 0; j < 4; j++) acc[i][j] = 0.0f;

    int arow = m0 + (t >> 2);
    int akk  = (t & 3) << 2;
    float ascale = (arow < NN) ? g_scale[arow] : 0.0f;
    int bk  = t >> 4;
    int bc  = (t & 15) << 2;

    #pragma unroll
    for (int kc = 0; kc < DIM; kc += 16) {
        // load A tile (scaled), store transposed
        float4 av = make_float4(0.f, 0.f, 0.f, 0.f);
        if (arow < NN)
            av = *(const float4*)(x + (size_t)arow * DIM + kc + akk);
        As[akk + 0][t >> 2] = av.x * ascale;
        As[akk + 1][t >> 2] = av.y * ascale;
        As[akk + 2][t >> 2] = av.z * ascale;
        As[akk + 3][t >> 2] = av.w * ascale;
        // load B tile
        float4 bv = *(const float4*)(g_wcat + (kc + bk) * NCOLS + n0 + bc);
        *(float4*)&Bs[bk][bc] = bv;
        __syncthreads();

        #pragma unroll
        for (int k = 0; k < 16; k++) {
            float4 a = *(const float4*)&As[k][ty << 2];
            float4 b = *(const float4*)&Bs[k][tx << 2];
            acc[0][0] += a.x * b.x; acc[0][1] += a.x * b.y; acc[0][2] += a.x * b.z; acc[0][3] += a.x * b.w;
            acc[1][0] += a.y * b.x; acc[1][1] += a.y * b.y; acc[1][2] += a.y * b.z; acc[1][3] += a.y * b.w;
            acc[2][0] += a.z * b.x; acc[2][1] += a.z * b.y; acc[2][2] += a.z * b.z; acc[2][3] += a.z * b.w;
            acc[3][0] += a.w * b.x; acc[3][1] += a.w * b.y; acc[3][2] += a.w * b.z; acc[3][3] += a.w * b.w;
        }
        __syncthreads();
    }

    #pragma unroll
    for (int i = 0; i < 4; i++) {
        int row = m0 + (ty << 2) + i;
        if (row < NN)
            *(float4*)(g_xcat + (size_t)row * NCOLS + n0 + (tx << 2)) =
                make_float4(acc[i][0], acc[i][1], acc[i][2], acc[i][3]);
    }
}

// ---------------- K4: edge logits + atomic max ----------------
__global__ __launch_bounds__(256) void k_alpha(const int* __restrict__ ei,
                                               const float* __restrict__ att) {
    __shared__ float s_att[HC];
    if (threadIdx.x < HC) s_att[threadIdx.x] = att[threadIdx.x];
    __syncthreads();

    int e    = (blockIdx.x * blockDim.x + threadIdx.x) >> 5;
    int lane = threadIdx.x & 31;
    if (e >= EE) return;
    int src = ei[e];
    int dst = ei[EE + e];

    const float4* xl = (const float4*)(g_xcat + (size_t)src * NCOLS);        // x_l
    const float4* xr = (const float4*)(g_xcat + (size_t)dst * NCOLS + HC);   // x_r
    const float4* a4 = (const float4*)s_att;

    // head 0: float4 slots [0,32) ; head 1: slots [32,64)
    float4 l0 = xl[lane],      r0 = xr[lane],      t0 = a4[lane];
    float4 l1 = xl[lane + 32], r1 = xr[lane + 32], t1 = a4[lane + 32];

    float s, p0 = 0.f, p1 = 0.f;
    s = l0.x + r0.x; p0 += (s > 0.f ? s : NEG * s) * t0.x;
    s = l0.y + r0.y; p0 += (s > 0.f ? s : NEG * s) * t0.y;
    s = l0.z + r0.z; p0 += (s > 0.f ? s : NEG * s) * t0.z;
    s = l0.w + r0.w; p0 += (s > 0.f ? s : NEG * s) * t0.w;
    s = l1.x + r1.x; p1 += (s > 0.f ? s : NEG * s) * t1.x;
    s = l1.y + r1.y; p1 += (s > 0.f ? s : NEG * s) * t1.y;
    s = l1.z + r1.z; p1 += (s > 0.f ? s : NEG * s) * t1.z;
    s = l1.w + r1.w; p1 += (s > 0.f ? s : NEG * s) * t1.w;

    p0 = warp_sum(p0);
    p1 = warp_sum(p1);
    if (lane == 0) {
        g_alpha[e * 2 + 0] = p0;
        g_alpha[e * 2 + 1] = p1;
        atomicMax(&g_amax[dst * 2 + 0], f2o(p0));
        atomicMax(&g_amax[dst * 2 + 1], f2o(p1));
    }
}

// ---------------- K5: exp + denom ----------------
__global__ __launch_bounds__(256) void k_exp(const int* __restrict__ ei) {
    int idx = blockIdx.x * blockDim.x + threadIdx.x;   // over EE*2
    if (idx >= EE * 2) return;
    int e = idx >> 1, h = idx & 1;
    int dst = ei[EE + e];
    float m = o2f(g_amax[dst * 2 + h]);
    float ex = expf(g_alpha[idx] - m);
    g_ex[idx] = ex;
    atomicAdd(&g_denom[dst * 2 + h], ex);
}

// ---------------- K6: weighted scatter (head mean folded in) ----------------
__global__ __launch_bounds__(256) void k_scatter(const int* __restrict__ ei,
                                                 float* __restrict__ out) {
    int e    = (blockIdx.x * blockDim.x + threadIdx.x) >> 5;
    int lane = threadIdx.x & 31;
    if (e >= EE) return;
    int src = ei[e];
    int dst = ei[EE + e];

    float w0 = 0.5f * g_ex[e * 2 + 0] / (g_denom[dst * 2 + 0] + 1e-16f);
    float w1 = 0.5f * g_ex[e * 2 + 1] / (g_denom[dst * 2 + 1] + 1e-16f);

    const float4* xl = (const float4*)(g_xcat + (size_t)src * NCOLS);
    float4 a0 = xl[lane];        // head 0, cols [lane*4, +4)
    float4 a1 = xl[lane + 32];   // head 1, same cols

    float* o = out + (size_t)dst * DIM + (lane << 2);
    atomicAdd(o + 0, a0.x * w0 + a1.x * w1);
    atomicAdd(o + 1, a0.y * w0 + a1.y * w1);
    atomicAdd(o + 2, a0.z * w0 + a1.z * w1);
    atomicAdd(o + 3, a0.w * w0 + a1.w * w1);
}

// ---------------- launch ----------------
extern "C" void kernel_launch(void* const* d_in, const int* in_sizes, int n_in,
                              void* d_out, int out_size) {
    const float* x    = (const float*)d_in[0];
    const int*   ei   = (const int*)d_in[1];
    const float* rmsw = (const float*)d_in[2];
    const float* wl   = (const float*)d_in[3];
    const float* wr   = (const float*)d_in[4];
    const float* att  = (const float*)d_in[5];
    float* out = (float*)d_out;

    k_init<<<4096, 256>>>(out);
    k_scale<<<(NN * 32 + 255) / 256, 256>>>(x);
    k_fold<<<(DIM * NCOLS + 255) / 256, 256>>>(rmsw, wl, wr);
    {
        dim3 grid(NCOLS / 64, (NN + 63) / 64);
        k_gemm<<<grid, 256>>>(x);
    }
    k_alpha<<<(EE * 32 + 255) / 256, 256>>>(ei, att);
    k_exp<<<(EE * 2 + 255) / 256, 256>>>(ei);
    k_scatter<<<(EE * 32 + 255) / 256, 256>>>(ei, out);
}

// round 2
// speedup vs baseline: 1.0280x; 1.0280x over previous
#include <cuda_runtime.h>
#include <cuda_bf16.h>

// Problem constants (fixed by the dataset)
#define NN      50000      // nodes
#define EE      600000     // edges
#define DIM     128        // input/hidden dim
#define HC      256        // H*C
#define NCOLS   512        // 2*H*C (x_l | x_r)
#define NEG     0.2f
#define RMS_EPS 1e-6f

// ---------------- scratch (static device allocations) ----------------
__device__ float    g_scale[NN];                       // rms row scale
__device__ float    g_wcat[DIM * NCOLS];               // rmsw-folded [W_l | W_r]
__device__ float    g_xcat[(size_t)NN * NCOLS];        // per node: [x_l(256) | x_r(256)]
__device__ float    g_alpha[EE * 2];                   // per-edge logits
__device__ float    g_ex[EE * 2];                      // per-edge exp numerators
__device__ unsigned g_amax[NN * 2];                    // order-encoded float max
__device__ float    g_denom[NN * 2];                   // softmax denominators

// ---------------- helpers ----------------
__device__ __forceinline__ unsigned f2o(float f) {
    unsigned u = __float_as_uint(f);
    return (u & 0x80000000u) ? ~u : (u | 0x80000000u);
}
__device__ __forceinline__ float o2f(unsigned u) {
    return (u & 0x80000000u) ? __uint_as_float(u & 0x7FFFFFFFu)
                             : __uint_as_float(~u);
}
__device__ __forceinline__ float warp_sum(float v) {
    #pragma unroll
    for (int off = 16; off; off >>= 1) v += __shfl_down_sync(0xffffffffu, v, off);
    return v;
}

// ---------------- K0: init (zero d_out, amax, denom) ----------------
__global__ void k_init(float* __restrict__ out) {
    int idx = blockIdx.x * blockDim.x + threadIdx.x;
    int stride = gridDim.x * blockDim.x;
    for (int i = idx; i < NN * DIM; i += stride) out[i] = 0.0f;
    for (int i = idx; i < NN * 2; i += stride) { g_amax[i] = 0u; g_denom[i] = 0.0f; }
}

// ---------------- K1: per-row RMS scale ----------------
__global__ __launch_bounds__(256) void k_scale(const float* __restrict__ x) {
    int warp = (blockIdx.x * blockDim.x + threadIdx.x) >> 5;
    int lane = threadIdx.x & 31;
    if (warp >= NN) return;
    const float4* xr = (const float4*)(x + (size_t)warp * DIM);
    float4 v = xr[lane];
    float s = v.x * v.x + v.y * v.y + v.z * v.z + v.w * v.w;
    s = warp_sum(s);
    if (lane == 0) g_scale[warp] = rsqrtf(s * (1.0f / DIM) + RMS_EPS);
}

// ---------------- K2: fold rms_weight into [W_l | W_r] ----------------
__global__ void k_fold(const float* __restrict__ rmsw,
                       const float* __restrict__ wl,
                       const float* __restrict__ wr) {
    int idx = blockIdx.x * blockDim.x + threadIdx.x;   // over DIM*NCOLS
    if (idx >= DIM * NCOLS) return;
    int k = idx / NCOLS, j = idx % NCOLS;
    float w = (j < HC) ? wl[k * HC + j] : wr[k * HC + (j - HC)];
    g_wcat[idx] = rmsw[k] * w;
}

// ---------------- K3: GEMM  xcat = (x*scale) @ wcat  (fp32) ----------------
// BM=128, BN=128, BK=8, 256 threads, 8x8 per-thread microtile.
// 4 LDS.128 per 64 FFMA = 1 B/FLOP of shared traffic (was 2 B/FLOP).
__global__ __launch_bounds__(256, 2) void k_gemm(const float* __restrict__ x) {
    __shared__ float As[8][128];   // transposed: [k][m]
    __shared__ float Bs[8][128];

    const int t  = threadIdx.x;
    const int n0 = blockIdx.x * 128;
    const int m0 = blockIdx.y * 128;
    const int tx = t & 15;          // 0..15  -> column group (8 cols)
    const int ty = t >> 4;          // 0..15  -> row group   (8 rows)

    float acc[8][8];
    #pragma unroll
    for (int i = 0; i < 8; i++)
        #pragma unroll
        for (int j = 0; j < 8; j++) acc[i][j] = 0.0f;

    // A loader: thread t loads float4 at (row m0 + t/2, k kc + (t&1)*4)
    const int ar   = t >> 1;              // 0..127
    const int ak   = (t & 1) << 2;        // 0 or 4
    const int arow = m0 + ar;
    const float ascale = (arow < NN) ? g_scale[arow] : 0.0f;
    const float* aptr = x + (size_t)arow * DIM + ak;

    // B loader: thread t loads float4 at (k kc + t/32, col n0 + (t&31)*4)
    const int bk = t >> 5;                // 0..7
    const int bc = (t & 31) << 2;         // 0..124
    const float* bptr = g_wcat + (size_t)bk * NCOLS + n0 + bc;

    #pragma unroll 4
    for (int kc = 0; kc < DIM; kc += 8) {
        float4 av = make_float4(0.f, 0.f, 0.f, 0.f);
        if (arow < NN) av = *(const float4*)(aptr + kc);
        As[ak + 0][ar] = av.x * ascale;
        As[ak + 1][ar] = av.y * ascale;
        As[ak + 2][ar] = av.z * ascale;
        As[ak + 3][ar] = av.w * ascale;

        float4 bv = *(const float4*)(bptr + (size_t)kc * NCOLS);
        *(float4*)&Bs[bk][bc] = bv;
        __syncthreads();

        #pragma unroll
        for (int k = 0; k < 8; k++) {
            float4 a0 = *(const float4*)&As[k][ty << 3];
            float4 a1 = *(const float4*)&As[k][(ty << 3) + 4];
            float4 b0 = *(const float4*)&Bs[k][tx << 3];
            float4 b1 = *(const float4*)&Bs[k][(tx << 3) + 4];
            float a[8] = {a0.x, a0.y, a0.z, a0.w, a1.x, a1.y, a1.z, a1.w};
            float b[8] = {b0.x, b0.y, b0.z, b0.w, b1.x, b1.y, b1.z, b1.w};
            #pragma unroll
            for (int i = 0; i < 8; i++)
                #pragma unroll
                for (int j = 0; j < 8; j++)
                    acc[i][j] += a[i] * b[j];
        }
        __syncthreads();
    }

    #pragma unroll
    for (int i = 0; i < 8; i++) {
        int row = m0 + (ty << 3) + i;
        if (row < NN) {
            float* o = g_xcat + (size_t)row * NCOLS + n0 + (tx << 3);
            *(float4*)(o + 0) = make_float4(acc[i][0], acc[i][1], acc[i][2], acc[i][3]);
            *(float4*)(o + 4) = make_float4(acc[i][4], acc[i][5], acc[i][6], acc[i][7]);
        }
    }
}

// ---------------- K4: edge logits + atomic max ----------------
__global__ __launch_bounds__(256) void k_alpha(const int* __restrict__ ei,
                                               const float* __restrict__ att) {
    __shared__ float s_att[HC];
    if (threadIdx.x < HC) s_att[threadIdx.x] = att[threadIdx.x];
    __syncthreads();

    int e    = (blockIdx.x * blockDim.x + threadIdx.x) >> 5;
    int lane = threadIdx.x & 31;
    if (e >= EE) return;
    int src = ei[e];
    int dst = ei[EE + e];

    const float4* xl = (const float4*)(g_xcat + (size_t)src * NCOLS);        // x_l
    const float4* xr = (const float4*)(g_xcat + (size_t)dst * NCOLS + HC);   // x_r
    const float4* a4 = (const float4*)s_att;

    // head 0: float4 slots [0,32) ; head 1: slots [32,64)
    float4 l0 = xl[lane],      r0 = xr[lane],      t0 = a4[lane];
    float4 l1 = xl[lane + 32], r1 = xr[lane + 32], t1 = a4[lane + 32];

    float s, p0 = 0.f, p1 = 0.f;
    s = l0.x + r0.x; p0 += (s > 0.f ? s : NEG * s) * t0.x;
    s = l0.y + r0.y; p0 += (s > 0.f ? s : NEG * s) * t0.y;
    s = l0.z + r0.z; p0 += (s > 0.f ? s : NEG * s) * t0.z;
    s = l0.w + r0.w; p0 += (s > 0.f ? s : NEG * s) * t0.w;
    s = l1.x + r1.x; p1 += (s > 0.f ? s : NEG * s) * t1.x;
    s = l1.y + r1.y; p1 += (s > 0.f ? s : NEG * s) * t1.y;
    s = l1.z + r1.z; p1 += (s > 0.f ? s : NEG * s) * t1.z;
    s = l1.w + r1.w; p1 += (s > 0.f ? s : NEG * s) * t1.w;

    p0 = warp_sum(p0);
    p1 = warp_sum(p1);
    if (lane == 0) {
        g_alpha[e * 2 + 0] = p0;
        g_alpha[e * 2 + 1] = p1;
        atomicMax(&g_amax[dst * 2 + 0], f2o(p0));
        atomicMax(&g_amax[dst * 2 + 1], f2o(p1));
    }
}

// ---------------- K5: exp + denom ----------------
__global__ __launch_bounds__(256) void k_exp(const int* __restrict__ ei) {
    int idx = blockIdx.x * blockDim.x + threadIdx.x;   // over EE*2
    if (idx >= EE * 2) return;
    int e = idx >> 1, h = idx & 1;
    int dst = ei[EE + e];
    float m = o2f(g_amax[dst * 2 + h]);
    float ex = expf(g_alpha[idx] - m);
    g_ex[idx] = ex;
    atomicAdd(&g_denom[dst * 2 + h], ex);
}

// ---------------- K6: weighted scatter (head mean folded in) ----------------
__global__ __launch_bounds__(256) void k_scatter(const int* __restrict__ ei,
                                                 float* __restrict__ out) {
    int e    = (blockIdx.x * blockDim.x + threadIdx.x) >> 5;
    int lane = threadIdx.x & 31;
    if (e >= EE) return;
    int src = ei[e];
    int dst = ei[EE + e];

    float w0 = 0.5f * g_ex[e * 2 + 0] / (g_denom[dst * 2 + 0] + 1e-16f);
    float w1 = 0.5f * g_ex[e * 2 + 1] / (g_denom[dst * 2 + 1] + 1e-16f);

    const float4* xl = (const float4*)(g_xcat + (size_t)src * NCOLS);
    float4 a0 = xl[lane];        // head 0, cols [lane*4, +4)
    float4 a1 = xl[lane + 32];   // head 1, same cols

    float* o = out + (size_t)dst * DIM + (lane << 2);
    atomicAdd(o + 0, a0.x * w0 + a1.x * w1);
    atomicAdd(o + 1, a0.y * w0 + a1.y * w1);
    atomicAdd(o + 2, a0.z * w0 + a1.z * w1);
    atomicAdd(o + 3, a0.w * w0 + a1.w * w1);
}

// ---------------- launch ----------------
extern "C" void kernel_launch(void* const* d_in, const int* in_sizes, int n_in,
                              void* d_out, int out_size) {
    const float* x    = (const float*)d_in[0];
    const int*   ei   = (const int*)d_in[1];
    const float* rmsw = (const float*)d_in[2];
    const float* wl   = (const float*)d_in[3];
    const float* wr   = (const float*)d_in[4];
    const float* att  = (const float*)d_in[5];
    float* out = (float*)d_out;

    k_init<<<4096, 256>>>(out);
    k_scale<<<(NN * 32 + 255) / 256, 256>>>(x);
    k_fold<<<(DIM * NCOLS + 255) / 256, 256>>>(rmsw, wl, wr);
    {
        dim3 grid(NCOLS / 128, (NN + 127) / 128);
        k_gemm<<<grid, 256>>>(x);
    }
    k_alpha<<<(EE * 32 + 255) / 256, 256>>>(ei, att);
    k_exp<<<(EE * 2 + 255) / 256, 256>>>(ei);
    k_scatter<<<(EE * 32 + 255) / 256, 256>>>(ei, out);
}

// round 3
// speedup vs baseline: 1.6134x; 1.5694x over previous
#include <cuda_runtime.h>
#include <cuda_bf16.h>

// Problem constants (fixed by the dataset)
#define NN      50000      // nodes
#define EE      600000     // edges
#define DIM     128        // input/hidden dim
#define HC      256        // H*C
#define NCOLS   512        // 2*H*C (x_l | x_r)
#define NEG     0.2f
#define RMS_EPS 1e-6f

#define SCAN_BPB 2048      // elements per scan block
#define NBLK_SCAN ((NN + SCAN_BPB - 1) / SCAN_BPB)   // 25

// ---------------- scratch (static device allocations) ----------------
__device__ float g_scale[NN];                       // rms row scale
__device__ float g_wcat[DIM * NCOLS];               // rmsw-folded [W_l | W_r]
__device__ float g_xcat[(size_t)NN * NCOLS];        // per node: [x_l(256) | x_r(256)]
__device__ int   g_deg[NN];                         // in-degree
__device__ int   g_cursor[NN];                      // fill cursors
__device__ int   g_rowptr[NN + 1];                  // CSR row pointers (by dst)
__device__ int   g_bsum[NBLK_SCAN];                 // scan block sums
__device__ int   g_boff[NBLK_SCAN];                 // scan block offsets
__device__ int   g_csrsrc[EE];                      // src ids sorted by dst

// ---------------- helpers ----------------
__device__ __forceinline__ float warp_sum(float v) {
    #pragma unroll
    for (int off = 16; off; off >>= 1) v += __shfl_down_sync(0xffffffffu, v, off);
    return v;
}

// ---------------- K0: init (zero deg + cursor) ----------------
__global__ void k_init() {
    int idx = blockIdx.x * blockDim.x + threadIdx.x;
    int stride = gridDim.x * blockDim.x;
    for (int i = idx; i < NN; i += stride) { g_deg[i] = 0; g_cursor[i] = 0; }
}

// ---------------- K1: per-row RMS scale ----------------
__global__ __launch_bounds__(256) void k_scale(const float* __restrict__ x) {
    int warp = (blockIdx.x * blockDim.x + threadIdx.x) >> 5;
    int lane = threadIdx.x & 31;
    if (warp >= NN) return;
    const float4* xr = (const float4*)(x + (size_t)warp * DIM);
    float4 v = xr[lane];
    float s = v.x * v.x + v.y * v.y + v.z * v.z + v.w * v.w;
    s = warp_sum(s);
    s = __shfl_sync(0xffffffffu, s, 0);
    if (lane == 0) g_scale[warp] = rsqrtf(s * (1.0f / DIM) + RMS_EPS);
}

// ---------------- K2: fold rms_weight into [W_l | W_r] ----------------
__global__ void k_fold(const float* __restrict__ rmsw,
                       const float* __restrict__ wl,
                       const float* __restrict__ wr) {
    int idx = blockIdx.x * blockDim.x + threadIdx.x;   // over DIM*NCOLS
    if (idx >= DIM * NCOLS) return;
    int k = idx / NCOLS, j = idx % NCOLS;
    float w = (j < HC) ? wl[k * HC + j] : wr[k * HC + (j - HC)];
    g_wcat[idx] = rmsw[k] * w;
}

// ---------------- K3: GEMM  xcat = (x*scale) @ wcat  (fp32) ----------------
__global__ __launch_bounds__(256, 2) void k_gemm(const float* __restrict__ x) {
    __shared__ float As[8][128];   // transposed: [k][m]
    __shared__ float Bs[8][128];

    const int t  = threadIdx.x;
    const int n0 = blockIdx.x * 128;
    const int m0 = blockIdx.y * 128;
    const int tx = t & 15;
    const int ty = t >> 4;

    float acc[8][8];
    #pragma unroll
    for (int i = 0; i < 8; i++)
        #pragma unroll
        for (int j = 0; j < 8; j++) acc[i][j] = 0.0f;

    const int ar   = t >> 1;
    const int ak   = (t & 1) << 2;
    const int arow = m0 + ar;
    const float ascale = (arow < NN) ? g_scale[arow] : 0.0f;
    const float* aptr = x + (size_t)arow * DIM + ak;

    const int bk = t >> 5;
    const int bc = (t & 31) << 2;
    const float* bptr = g_wcat + (size_t)bk * NCOLS + n0 + bc;

    #pragma unroll 4
    for (int kc = 0; kc < DIM; kc += 8) {
        float4 av = make_float4(0.f, 0.f, 0.f, 0.f);
        if (arow < NN) av = *(const float4*)(aptr + kc);
        As[ak + 0][ar] = av.x * ascale;
        As[ak + 1][ar] = av.y * ascale;
        As[ak + 2][ar] = av.z * ascale;
        As[ak + 3][ar] = av.w * ascale;

        float4 bv = *(const float4*)(bptr + (size_t)kc * NCOLS);
        *(float4*)&Bs[bk][bc] = bv;
        __syncthreads();

        #pragma unroll
        for (int k = 0; k < 8; k++) {
            float4 a0 = *(const float4*)&As[k][ty << 3];
            float4 a1 = *(const float4*)&As[k][(ty << 3) + 4];
            float4 b0 = *(const float4*)&Bs[k][tx << 3];
            float4 b1 = *(const float4*)&Bs[k][(tx << 3) + 4];
            float a[8] = {a0.x, a0.y, a0.z, a0.w, a1.x, a1.y, a1.z, a1.w};
            float b[8] = {b0.x, b0.y, b0.z, b0.w, b1.x, b1.y, b1.z, b1.w};
            #pragma unroll
            for (int i = 0; i < 8; i++)
                #pragma unroll
                for (int j = 0; j < 8; j++)
                    acc[i][j] += a[i] * b[j];
        }
        __syncthreads();
    }

    #pragma unroll
    for (int i = 0; i < 8; i++) {
        int row = m0 + (ty << 3) + i;
        if (row < NN) {
            float* o = g_xcat + (size_t)row * NCOLS + n0 + (tx << 3);
            *(float4*)(o + 0) = make_float4(acc[i][0], acc[i][1], acc[i][2], acc[i][3]);
            *(float4*)(o + 4) = make_float4(acc[i][4], acc[i][5], acc[i][6], acc[i][7]);
        }
    }
}

// ---------------- K4: degree histogram ----------------
__global__ void k_hist(const int* __restrict__ ei) {
    int e = blockIdx.x * blockDim.x + threadIdx.x;
    if (e >= EE) return;
    atomicAdd(&g_deg[ei[EE + e]], 1);
}

// ---------------- K5a: per-block exclusive scan ----------------
__global__ __launch_bounds__(256) void k_scan_block() {
    __shared__ int ssum[256];
    int base  = blockIdx.x * SCAN_BPB;
    int tbase = base + threadIdx.x * 8;
    int local[8];
    int run = 0;
    #pragma unroll
    for (int i = 0; i < 8; i++) {
        int v = (tbase + i < NN) ? g_deg[tbase + i] : 0;
        local[i] = run;
        run += v;
    }
    int myrun = run;
    ssum[threadIdx.x] = run;
    __syncthreads();
    #pragma unroll
    for (int off = 1; off < 256; off <<= 1) {
        int v = (threadIdx.x >= off) ? ssum[threadIdx.x - off] : 0;
        __syncthreads();
        ssum[threadIdx.x] += v;
        __syncthreads();
    }
    int excl = ssum[threadIdx.x] - myrun;
    #pragma unroll
    for (int i = 0; i < 8; i++)
        if (tbase + i < NN) g_rowptr[tbase + i] = excl + local[i];
    if (threadIdx.x == 255) g_bsum[blockIdx.x] = ssum[255];
}

// ---------------- K5b: scan block sums (tiny) ----------------
__global__ void k_scan_top() {
    if (threadIdx.x == 0) {
        int run = 0;
        for (int b = 0; b < NBLK_SCAN; b++) {
            int v = g_bsum[b];
            g_boff[b] = run;
            run += v;
        }
    }
}

// ---------------- K5c: add block offsets ----------------
__global__ void k_scan_add() {
    int idx = blockIdx.x * blockDim.x + threadIdx.x;
    if (idx < NN) g_rowptr[idx] += g_boff[idx / SCAN_BPB];
    if (idx == 0) g_rowptr[NN] = EE;
}

// ---------------- K6: fill CSR (src ids grouped by dst) ----------------
__global__ void k_fill(const int* __restrict__ ei) {
    int e = blockIdx.x * blockDim.x + threadIdx.x;
    if (e >= EE) return;
    int dst = ei[EE + e];
    int pos = g_rowptr[dst] + atomicAdd(&g_cursor[dst], 1);
    g_csrsrc[pos] = ei[e];
}

// ---------------- K7: fused edge pass (online softmax + aggregate) ----------------
// One warp per destination node. No atomics anywhere.
__global__ __launch_bounds__(256) void k_edge(const float* __restrict__ att,
                                              float* __restrict__ out) {
    int node = (blockIdx.x * blockDim.x + threadIdx.x) >> 5;
    int lane = threadIdx.x & 31;
    if (node >= NN) return;

    const float4* a4 = (const float4*)att;
    float4 t0 = __ldg(&a4[lane]);          // att head 0, cols [lane*4,+4)
    float4 t1 = __ldg(&a4[lane + 32]);     // att head 1

    const float4* xr = (const float4*)(g_xcat + (size_t)node * NCOLS + HC);
    float4 r0 = xr[lane];
    float4 r1 = xr[lane + 32];

    float m0 = -__int_as_float(0x7f800000), m1 = m0;   // -inf
    float s0 = 0.f, s1 = 0.f;
    float4 A0 = make_float4(0.f, 0.f, 0.f, 0.f);
    float4 A1 = make_float4(0.f, 0.f, 0.f, 0.f);

    int beg = g_rowptr[node];
    int end = g_rowptr[node + 1];

    for (int j = beg; j < end; j++) {
        int src = g_csrsrc[j];
        const float4* xl = (const float4*)(g_xcat + (size_t)src * NCOLS);
        float4 l0 = xl[lane];
        float4 l1 = xl[lane + 32];

        float v, p0 = 0.f, p1 = 0.f;
        v = l0.x + r0.x; p0 += (v > 0.f ? v : NEG * v) * t0.x;
        v = l0.y + r0.y; p0 += (v > 0.f ? v : NEG * v) * t0.y;
        v = l0.z + r0.z; p0 += (v > 0.f ? v : NEG * v) * t0.z;
        v = l0.w + r0.w; p0 += (v > 0.f ? v : NEG * v) * t0.w;
        v = l1.x + r1.x; p1 += (v > 0.f ? v : NEG * v) * t1.x;
        v = l1.y + r1.y; p1 += (v > 0.f ? v : NEG * v) * t1.y;
        v = l1.z + r1.z; p1 += (v > 0.f ? v : NEG * v) * t1.z;
        v = l1.w + r1.w; p1 += (v > 0.f ? v : NEG * v) * t1.w;

        // butterfly reduce — all lanes end with the full logits
        #pragma unroll
        for (int off = 16; off; off >>= 1) {
            p0 += __shfl_xor_sync(0xffffffffu, p0, off);
            p1 += __shfl_xor_sync(0xffffffffu, p1, off);
        }

        // online softmax update, head 0
        float nm0 = fmaxf(m0, p0);
        float c0  = __expf(m0 - nm0);   // 0 on first edge (m0 = -inf, nm0 finite)
        float w0  = __expf(p0 - nm0);
        s0 = s0 * c0 + w0;
        A0.x = A0.x * c0 + w0 * l0.x;
        A0.y = A0.y * c0 + w0 * l0.y;
        A0.z = A0.z * c0 + w0 * l0.z;
        A0.w = A0.w * c0 + w0 * l0.w;
        m0 = nm0;
        // head 1
        float nm1 = fmaxf(m1, p1);
        float c1  = __expf(m1 - nm1);
        float w1  = __expf(p1 - nm1);
        s1 = s1 * c1 + w1;
        A1.x = A1.x * c1 + w1 * l1.x;
        A1.y = A1.y * c1 + w1 * l1.y;
        A1.z = A1.z * c1 + w1 * l1.z;
        A1.w = A1.w * c1 + w1 * l1.w;
        m1 = nm1;
    }

    float i0 = 0.5f / (s0 + 1e-16f);
    float i1 = 0.5f / (s1 + 1e-16f);
    float4 o;
    o.x = A0.x * i0 + A1.x * i1;
    o.y = A0.y * i0 + A1.y * i1;
    o.z = A0.z * i0 + A1.z * i1;
    o.w = A0.w * i0 + A1.w * i1;
    *(float4*)(out + (size_t)node * DIM + (lane << 2)) = o;
}

// ---------------- launch ----------------
extern "C" void kernel_launch(void* const* d_in, const int* in_sizes, int n_in,
                              void* d_out, int out_size) {
    const float* x    = (const float*)d_in[0];
    const int*   ei   = (const int*)d_in[1];
    const float* rmsw = (const float*)d_in[2];
    const float* wl   = (const float*)d_in[3];
    const float* wr   = (const float*)d_in[4];
    const float* att  = (const float*)d_in[5];
    float* out = (float*)d_out;

    k_init<<<256, 256>>>();
    k_scale<<<(NN * 32 + 255) / 256, 256>>>(x);
    k_fold<<<(DIM * NCOLS + 255) / 256, 256>>>(rmsw, wl, wr);
    {
        dim3 grid(NCOLS / 128, (NN + 127) / 128);
        k_gemm<<<grid, 256>>>(x);
    }
    k_hist<<<(EE + 255) / 256, 256>>>(ei);
    k_scan_block<<<NBLK_SCAN, 256>>>();
    k_scan_top<<<1, 32>>>();
    k_scan_add<<<(NN + 255) / 256, 256>>>();
    k_fill<<<(EE + 255) / 256, 256>>>(ei);
    k_edge<<<(NN * 32 + 255) / 256, 256>>>(att, out);
}